// round 1
// baseline (speedup 1.0000x reference)
#include <cuda_runtime.h>

// Problem constants (fixed by the reference)
#define BATCH 16
#define CIN   128
#define COUT  128
#define Hh    224
#define Ww    224
#define PLANE (Hh * Ww)          // 50176 floats per (b,c) plane
#define PLANE4 (PLANE / 4)       // 12544 float4 per plane
#define W4    (Ww / 4)           // 56 float4 per row

// Scratch for channel-sum C[b][h][w]  (16 * 50176 floats = ~51 MB)
__device__ float g_S[BATCH * PLANE];

// ---------------------------------------------------------------------------
// Kernel 1: C[b,h,w] = sum_c x[b,c,h,w]   (float4 per thread)
// ---------------------------------------------------------------------------
__global__ __launch_bounds__(256) void channel_sum_kernel(const float* __restrict__ x) {
    int p = blockIdx.x * blockDim.x + threadIdx.x;     // float4 index over B*PLANE4
    if (p >= BATCH * PLANE4) return;
    int b   = p / PLANE4;
    int sp4 = p - b * PLANE4;

    const float4* xb = reinterpret_cast<const float4*>(x) + (size_t)b * CIN * PLANE4 + sp4;

    float4 acc = make_float4(0.f, 0.f, 0.f, 0.f);
#pragma unroll 8
    for (int c = 0; c < CIN; c++) {
        float4 v = __ldg(xb + (size_t)c * PLANE4);
        acc.x += v.x; acc.y += v.y; acc.z += v.z; acc.w += v.w;
    }
    reinterpret_cast<float4*>(g_S)[(size_t)b * PLANE4 + sp4] = acc;
}

// ---------------------------------------------------------------------------
// Kernel 2: out[b,o,h,w] = cross-stencil(C)[b,h,w] + bias[o]
// Each thread computes one float4 stencil result and broadcasts it to all
// 128 output channels (coalesced float4 stores per channel).
// ---------------------------------------------------------------------------
__global__ __launch_bounds__(256) void stencil_broadcast_kernel(const float* __restrict__ bias,
                                                                float* __restrict__ out) {
    __shared__ float sb[COUT];
    if (threadIdx.x < COUT) sb[threadIdx.x] = bias[threadIdx.x];
    __syncthreads();

    int p = blockIdx.x * blockDim.x + threadIdx.x;     // float4 index over B*PLANE4
    if (p >= BATCH * PLANE4) return;
    int b   = p / PLANE4;
    int sp4 = p - b * PLANE4;
    int h   = sp4 / W4;
    int w4  = sp4 - h * W4;

    const float*  Sb  = g_S + (size_t)b * PLANE;
    const float4* Sb4 = reinterpret_cast<const float4*>(Sb);

    float4 c = Sb4[sp4];
    float4 u = (h > 0)      ? Sb4[sp4 - W4] : make_float4(0.f, 0.f, 0.f, 0.f);
    float4 d = (h < Hh - 1) ? Sb4[sp4 + W4] : make_float4(0.f, 0.f, 0.f, 0.f);
    float  lm = (w4 > 0)      ? Sb[h * Ww + w4 * 4 - 1] : 0.f;
    float  rp = (w4 < W4 - 1) ? Sb[h * Ww + w4 * 4 + 4] : 0.f;

    float4 r;
    r.x = u.x + d.x + lm  + c.y + c.x;
    r.y = u.y + d.y + c.x + c.z + c.y;
    r.z = u.z + d.z + c.y + c.w + c.z;
    r.w = u.w + d.w + c.z + rp  + c.w;

    float4* ob = reinterpret_cast<float4*>(out) + (size_t)b * COUT * PLANE4 + sp4;
#pragma unroll 4
    for (int o = 0; o < COUT; o++) {
        float bo = sb[o];
        float4 v = make_float4(r.x + bo, r.y + bo, r.z + bo, r.w + bo);
        ob[(size_t)o * PLANE4] = v;
    }
}

extern "C" void kernel_launch(void* const* d_in, const int* in_sizes, int n_in,
                              void* d_out, int out_size) {
    const float* x    = (const float*)d_in[0];   // [16,128,224,224] f32
    const float* bias = (const float*)d_in[2];   // [128] f32
    float* out = (float*)d_out;                  // [16,128,224,224] f32

    const int n4 = BATCH * PLANE4;               // 200704
    const int threads = 256;
    const int blocks = (n4 + threads - 1) / threads;

    channel_sum_kernel<<<blocks, threads>>>(x);
    stencil_broadcast_kernel<<<blocks, threads>>>(bias, out);
}